// round 1
// baseline (speedup 1.0000x reference)
#include <cuda_runtime.h>

#define RADIUS 5
#define KSZ    11
#define TX     32
#define TY     8
#define SW     (TX + 2*RADIUS)   /* 42 */
#define SH     (TY + 2*RADIUS)   /* 18 */
#define NB     8
#define NK     4
#define IMH    224
#define IMW    224

// Global accumulators: [b][k][{A,B}] as double. (Device global, no allocation.)
__device__ double g_acc[NB * NK * 2];

__global__ void k_zero() {
    int i = threadIdx.x;
    if (i < NB * NK * 2) g_acc[i] = 0.0;
}

__global__ __launch_bounds__(TX * TY) void k_main(const float* __restrict__ images,
                                                  const float* __restrict__ labels) {
    __shared__ float s_img[SH * SW];
    __shared__ float s_lab[NK][SH * SW];
    __shared__ float s_red[TY][8];

    const int tx  = threadIdx.x;
    const int ty  = threadIdx.y;
    const int tid = ty * TX + tx;
    const int b   = blockIdx.z;
    const int y0  = blockIdx.y * TY;
    const int x0  = blockIdx.x * TX;

    const float* imgb = images + (size_t)b * IMH * IMW;

    // Cooperative halo load. Out-of-image: image gets a huge sentinel so the
    // bilateral weight underflows to exactly 0 (implements the mask); labels 0.
    for (int i = tid; i < SH * SW; i += TX * TY) {
        int sy = i / SW;
        int sx = i - sy * SW;
        int gy = y0 + sy - RADIUS;
        int gx = x0 + sx - RADIUS;
        bool in = ((unsigned)gy < IMH) && ((unsigned)gx < IMW);
        int g = gy * IMW + gx;
        s_img[i] = in ? imgb[g] * 255.0f : 1e10f;
        #pragma unroll
        for (int k = 0; k < NK; k++)
            s_lab[k][i] = in ? labels[((size_t)b * NK + k) * IMH * IMW + g] : 0.0f;
    }
    __syncthreads();

    const int   cidx = (ty + RADIUS) * SW + tx + RADIUS;
    const float c    = s_img[cidx];
    const float pf0  = s_lab[0][cidx];
    const float pf1  = s_lab[1][cidx];
    const float pf2  = s_lab[2][cidx];
    const float pf3  = s_lab[3][cidx];

    float den = 0.f, n0 = 0.f, n1 = 0.f, n2 = 0.f, n3 = 0.f;

    #pragma unroll
    for (int dy = 0; dy < KSZ; dy++) {
        const int   base = (ty + dy) * SW + tx;
        const float fy2  = (float)((dy - RADIUS) * (dy - RADIUS));
        #pragma unroll
        for (int dx = 0; dx < KSZ; dx++) {
            const float d2   = fy2 + (float)((dx - RADIUS) * (dx - RADIUS));
            const float r    = s_img[base + dx];
            const float diff = r - c;
            // w = exp(-(r-c)^2/100) * exp(-d2/16), folded into one exp
            const float arg = fmaf(diff * diff, -0.01f, -0.0625f * d2);
            const float w   = __expf(arg);
            den += w;
            n0 = fmaf(w, s_lab[0][base + dx], n0);
            n1 = fmaf(w, s_lab[1][base + dx], n1);
            n2 = fmaf(w, s_lab[2][base + dx], n2);
            n3 = fmaf(w, s_lab[3][base + dx], n3);
        }
    }

    // Per-thread contributions to the 8 per-(b) scalars.
    float v[8] = { pf0 * n0, pf1 * n1, pf2 * n2, pf3 * n3,
                   pf0 * den, pf1 * den, pf2 * den, pf3 * den };

    #pragma unroll
    for (int j = 0; j < 8; j++) {
        float s = v[j];
        #pragma unroll
        for (int o = 16; o > 0; o >>= 1)
            s += __shfl_xor_sync(0xffffffffu, s, o);
        if (tx == 0) s_red[ty][j] = s;
    }
    __syncthreads();

    if (tid < 8) {
        float s = 0.f;
        #pragma unroll
        for (int w = 0; w < TY; w++) s += s_red[w][tid];
        const int k     = tid & 3;
        const int which = tid >> 2;     // 0 = A (num side), 1 = B (den side)
        atomicAdd(&g_acc[(b * NK + k) * 2 + which], (double)s);
    }
}

__global__ void k_final(float* out) {
    if (threadIdx.x == 0) {
        double acc = 0.0;
        for (int b = 0; b < NB; b++)
            for (int k = 0; k < NK; k++) {
                double A  = g_acc[(b * NK + k) * 2 + 0];
                double Bv = g_acc[(b * NK + k) * 2 + 1];
                acc += fabs(A / Bv);
            }
        out[0] = (float)((double)NK - acc / (double)NB);
    }
}

extern "C" void kernel_launch(void* const* d_in, const int* in_sizes, int n_in,
                              void* d_out, int out_size) {
    const float* images = (const float*)d_in[0];
    const float* labels = (const float*)d_in[1];
    // Robust to input ordering: images has 8*1*224*224 elems, labels 4x that.
    if (n_in >= 2 && in_sizes[0] > in_sizes[1]) {
        images = (const float*)d_in[1];
        labels = (const float*)d_in[0];
    }

    k_zero<<<1, 64>>>();
    dim3 grid(IMW / TX, IMH / TY, NB);
    dim3 blk(TX, TY);
    k_main<<<grid, blk>>>(images, labels);
    k_final<<<1, 32>>>((float*)d_out);
}